// round 1
// baseline (speedup 1.0000x reference)
#include <cuda_runtime.h>

#define NN 20000
#define NE 320000
#define CS 128
#define CZ 64
#define CH 256
#define CV 16
#define K1 112          // 64 edge feats + 48 rotated src points
#define TILE 64         // edges per block in edge kernel
#define AP 112          // sA row pitch (floats)
#define KT 16           // k-tile for weight staging
#define NT 8            // nodes per block in node kernel

// -------- scratch (device globals; no allocation allowed) --------
__device__ float g_pre_d[NN * CH];   // b1 + scal_dst@W1a + loc_i@W1_I - u@S_J
__device__ float g_pre_s[NN * CH];   // scal_src@W1b
__device__ float g_vecs[NN * 48];    // global-frame points [N,16,3]
__device__ float g_Wcat[K1 * CH];    // [W1_edge(64); W1_j+W1_d(48)]
__device__ float g_SJ[3 * CH];       // column sums of W1J over channels
__device__ float g_sum[NN * CS];
__device__ float g_cnt[NN];

// -------- setup: derived weights --------
__global__ void k_setup(const float* __restrict__ W1) {
    int h = threadIdx.x;  // 256 threads, one output column each
    for (int r = 0; r < 64; r++)
        g_Wcat[r * CH + h] = W1[(256 + r) * CH + h];
    float sj0 = 0.f, sj1 = 0.f, sj2 = 0.f;
    for (int r = 0; r < 48; r++) {
        float v = W1[(368 + r) * CH + h] + W1[(416 + r) * CH + h];
        g_Wcat[(64 + r) * CH + h] = v;
        int i = r % 3;
        if (i == 0) sj0 += v; else if (i == 1) sj1 += v; else sj2 += v;
    }
    g_SJ[0 * CH + h] = sj0;
    g_SJ[1 * CH + h] = sj1;
    g_SJ[2 * CH + h] = sj2;
}

// -------- zero accumulators --------
__global__ void k_zero() {
    int i = blockIdx.x * blockDim.x + threadIdx.x;
    int stride = gridDim.x * blockDim.x;
    for (int j = i; j < NN * CS; j += stride) g_sum[j] = 0.f;
    for (int j = i; j < NN; j += stride) g_cnt[j] = 0.f;
}

// -------- node kernel: geometry + per-node precompute --------
__global__ void __launch_bounds__(256) k_node(
    const float* __restrict__ scal, const float* __restrict__ nvec,
    const float* __restrict__ rot, const float* __restrict__ trans,
    const float* __restrict__ Wpts, const float* __restrict__ bpts,
    const float* __restrict__ Wcomb, const float* __restrict__ Wspts,
    const float* __restrict__ W1, const float* __restrict__ b1,
    float* __restrict__ out_v)
{
    __shared__ float sScal[NT][CS];
    __shared__ float sRaw[NT][24];
    __shared__ float sCat[NT][72];
    __shared__ float sVec[NT][48];
    __shared__ float sLoc[NT][48];
    __shared__ float sU[NT][4];

    int tid = threadIdx.x;
    int g = tid >> 5, lane = tid & 31;
    int n = blockIdx.x * NT + g;

    // load scalars (warp per node)
    {
        float4* d4 = (float4*)sScal[g];
        const float4* s4 = (const float4*)(scal + (size_t)n * CS);
        for (int i = lane; i < CS / 4; i += 32) d4[i] = s4[i];
    }
    __syncwarp();

    // s_raw[24] = scal @ W_pts + b_pts
    if (lane < 24) {
        float acc = bpts[lane];
        for (int k = 0; k < CS; k++) acc += sScal[g][k] * Wpts[k * 24 + lane];
        sRaw[g][lane] = acc;
    }
    __syncwarp();

    float R[9];
#pragma unroll
    for (int j = 0; j < 9; j++) R[j] = rot[(size_t)n * 9 + j];
    float t0 = trans[n * 3 + 0], t1 = trans[n * 3 + 1], t2 = trans[n * 3 + 2];

    // vecs_cat: 16 node vectors + 8 rotated s_pts   (s[p,i] = sum_j R[i,j] raw[j*8+p])
    for (int idx = lane; idx < 72; idx += 32) {
        int c = idx / 3, d = idx % 3;
        float v;
        if (c < CV) {
            v = nvec[(size_t)n * 48 + idx];
        } else {
            int p = c - CV;
            v = R[d * 3 + 0] * sRaw[g][0 * 8 + p] + R[d * 3 + 1] * sRaw[g][1 * 8 + p]
              + R[d * 3 + 2] * sRaw[g][2 * 8 + p];
        }
        sCat[g][idx] = v;
    }
    __syncwarp();

    // vecs = cat@W_comb + trans/10 ; out_s_v = cat@W_spts
    for (int idx = lane; idx < 48; idx += 32) {
        int v = idx / 3, d = idx % 3;
        float td = (d == 0) ? t0 : (d == 1) ? t1 : t2;
        float acc = td * 0.1f;
        float acc2 = 0.f;
        for (int c = 0; c < 24; c++) {
            float cv = sCat[g][c * 3 + d];
            acc += cv * Wcomb[c * CV + v];
            acc2 += cv * Wspts[c * CV + v];
        }
        sVec[g][idx] = acc;
        g_vecs[(size_t)n * 48 + idx] = acc;
        out_v[(size_t)n * 48 + idx] = acc2;
    }
    __syncwarp();

    // loc_i[c,i] = sum_j R[j,i] (vecs[c,j] - t[j]);  u[i] = sum_j R[j,i] t[j]
    for (int idx = lane; idx < 48; idx += 32) {
        int c = idx / 3, i = idx % 3;
        float x0 = sVec[g][c * 3 + 0] - t0;
        float x1 = sVec[g][c * 3 + 1] - t1;
        float x2 = sVec[g][c * 3 + 2] - t2;
        sLoc[g][idx] = R[0 + i] * x0 + R[3 + i] * x1 + R[6 + i] * x2;
    }
    if (lane < 3) sU[g][lane] = R[0 + lane] * t0 + R[3 + lane] * t1 + R[6 + lane] * t2;
    __syncthreads();

    // phase 2: pre_d / pre_s, one output column per thread, 8 nodes together
    int h = tid;
    float ad[NT], as_[NT];
#pragma unroll
    for (int q = 0; q < NT; q++) { ad[q] = b1[h]; as_[q] = 0.f; }
    for (int k = 0; k < CS; k++) {
        float wa = W1[k * CH + h];
        float wb = W1[(CS + k) * CH + h];
#pragma unroll
        for (int q = 0; q < NT; q++) {
            float s = sScal[q][k];
            ad[q] += s * wa;
            as_[q] += s * wb;
        }
    }
    for (int r = 0; r < 48; r++) {
        float wI = W1[(320 + r) * CH + h] - W1[(416 + r) * CH + h];
#pragma unroll
        for (int q = 0; q < NT; q++) ad[q] += sLoc[q][r] * wI;
    }
#pragma unroll
    for (int i = 0; i < 3; i++) {
        float sj = g_SJ[i * CH + h];
#pragma unroll
        for (int q = 0; q < NT; q++) ad[q] -= sU[q][i] * sj;
    }
    int nb = blockIdx.x * NT;
#pragma unroll
    for (int q = 0; q < NT; q++) {
        g_pre_d[(size_t)(nb + q) * CH + h] = ad[q];
        g_pre_s[(size_t)(nb + q) * CH + h] = as_[q];
    }
}

// -------- edge kernel: 3 fused GEMMs + atomic scatter --------
__global__ void __launch_bounds__(256, 2) k_edge(
    const float* __restrict__ ef, const int* __restrict__ ei,
    const float* __restrict__ rot,
    const float* __restrict__ W2, const float* __restrict__ b2,
    const float* __restrict__ W3, const float* __restrict__ b3)
{
    extern __shared__ float sm[];
    float* sA = sm;                    // TILE*AP   = 7168 floats
    float* sH = sm + TILE * AP;        // TILE*CH   = 16384 floats
    float* sW = sH + TILE * CH;        // KT*CH     = 4096 floats
    __shared__ int sDst[TILE], sSrc[TILE];

    int tid = threadIdx.x;
    int e0 = blockIdx.x * TILE;
    if (tid < TILE) {
        sSrc[tid] = ei[e0 + tid];
        sDst[tid] = ei[NE + e0 + tid];
    }
    __syncthreads();

    // stage edge features into sA[:, 0:64]
    {
        const float4* ef4 = (const float4*)(ef + (size_t)e0 * CZ);
        for (int i = tid; i < TILE * CZ / 4; i += 256) {
            int row = i >> 4, c4 = i & 15;
            *(float4*)&sA[row * AP + c4 * 4] = ef4[row * 16 + c4];
        }
    }
    // y = R_dst^T vecs_src  into sA[:, 64:112]   (4 threads per edge)
    {
        int r = tid >> 2, q = tid & 3;
        int s = sSrc[r], d = sDst[r];
        float R[9];
#pragma unroll
        for (int j = 0; j < 9; j++) R[j] = rot[(size_t)d * 9 + j];
#pragma unroll
        for (int cc = 0; cc < 4; cc++) {
            int c = q * 4 + cc;
            float v0 = g_vecs[(size_t)s * 48 + c * 3 + 0];
            float v1 = g_vecs[(size_t)s * 48 + c * 3 + 1];
            float v2 = g_vecs[(size_t)s * 48 + c * 3 + 2];
#pragma unroll
            for (int i = 0; i < 3; i++)
                sA[r * AP + 64 + c * 3 + i] = R[0 + i] * v0 + R[3 + i] * v1 + R[6 + i] * v2;
        }
        if (q == 0) atomicAdd(&g_cnt[d], 1.0f);
    }
    __syncthreads();

    int ty = tid >> 5, tx = tid & 31;

    // ---- GEMM1: [64,112] x [112,256], acc init = pre_d[dst] + pre_s[src] ----
    float acc[8][8];
#pragma unroll
    for (int r = 0; r < 8; r++) {
        int row = ty * 8 + r;
        const float4* pd = (const float4*)(g_pre_d + (size_t)sDst[row] * CH + tx * 8);
        const float4* ps = (const float4*)(g_pre_s + (size_t)sSrc[row] * CH + tx * 8);
        float4 a0 = pd[0], a1 = pd[1], c0 = ps[0], c1 = ps[1];
        acc[r][0] = a0.x + c0.x; acc[r][1] = a0.y + c0.y;
        acc[r][2] = a0.z + c0.z; acc[r][3] = a0.w + c0.w;
        acc[r][4] = a1.x + c1.x; acc[r][5] = a1.y + c1.y;
        acc[r][6] = a1.z + c1.z; acc[r][7] = a1.w + c1.w;
    }
    for (int k0 = 0; k0 < K1; k0 += KT) {
        __syncthreads();
        for (int i = tid; i < KT * CH / 4; i += 256)
            ((float4*)sW)[i] = ((const float4*)(g_Wcat + k0 * CH))[i];
        __syncthreads();
#pragma unroll
        for (int kk = 0; kk < KT; kk++) {
            int k = k0 + kk;
            float av[8];
#pragma unroll
            for (int r = 0; r < 8; r++) av[r] = sA[(ty * 8 + r) * AP + k];
            float4 w0 = *(float4*)&sW[kk * CH + tx * 8];
            float4 w1 = *(float4*)&sW[kk * CH + tx * 8 + 4];
#pragma unroll
            for (int r = 0; r < 8; r++) {
                acc[r][0] += av[r] * w0.x; acc[r][1] += av[r] * w0.y;
                acc[r][2] += av[r] * w0.z; acc[r][3] += av[r] * w0.w;
                acc[r][4] += av[r] * w1.x; acc[r][5] += av[r] * w1.y;
                acc[r][6] += av[r] * w1.z; acc[r][7] += av[r] * w1.w;
            }
        }
    }
    __syncthreads();
#pragma unroll
    for (int r = 0; r < 8; r++)
#pragma unroll
        for (int c = 0; c < 8; c++)
            sH[(ty * 8 + r) * CH + tx * 8 + c] = fmaxf(acc[r][c], 0.f);
    __syncthreads();

    // ---- GEMM2: [64,256] x [256,256] ----
    float acc2[8][8];
    {
        float4 bb0 = *(const float4*)&b2[tx * 8];
        float4 bb1 = *(const float4*)&b2[tx * 8 + 4];
#pragma unroll
        for (int r = 0; r < 8; r++) {
            acc2[r][0] = bb0.x; acc2[r][1] = bb0.y; acc2[r][2] = bb0.z; acc2[r][3] = bb0.w;
            acc2[r][4] = bb1.x; acc2[r][5] = bb1.y; acc2[r][6] = bb1.z; acc2[r][7] = bb1.w;
        }
    }
    for (int k0 = 0; k0 < CH; k0 += KT) {
        __syncthreads();
        for (int i = tid; i < KT * CH / 4; i += 256)
            ((float4*)sW)[i] = ((const float4*)(W2 + k0 * CH))[i];
        __syncthreads();
#pragma unroll
        for (int kk = 0; kk < KT; kk++) {
            int k = k0 + kk;
            float av[8];
#pragma unroll
            for (int r = 0; r < 8; r++) av[r] = sH[(ty * 8 + r) * CH + k];
            float4 w0 = *(float4*)&sW[kk * CH + tx * 8];
            float4 w1 = *(float4*)&sW[kk * CH + tx * 8 + 4];
#pragma unroll
            for (int r = 0; r < 8; r++) {
                acc2[r][0] += av[r] * w0.x; acc2[r][1] += av[r] * w0.y;
                acc2[r][2] += av[r] * w0.z; acc2[r][3] += av[r] * w0.w;
                acc2[r][4] += av[r] * w1.x; acc2[r][5] += av[r] * w1.y;
                acc2[r][6] += av[r] * w1.z; acc2[r][7] += av[r] * w1.w;
            }
        }
    }
    __syncthreads();
#pragma unroll
    for (int r = 0; r < 8; r++)
#pragma unroll
        for (int c = 0; c < 8; c++)
            sH[(ty * 8 + r) * CH + tx * 8 + c] = fmaxf(acc2[r][c], 0.f);
    __syncthreads();

    // ---- GEMM3: [64,256] x [256,128], then atomic scatter ----
    float acc3[8][4];
    {
        float4 bb = *(const float4*)&b3[tx * 4];
#pragma unroll
        for (int r = 0; r < 8; r++) {
            acc3[r][0] = bb.x; acc3[r][1] = bb.y; acc3[r][2] = bb.z; acc3[r][3] = bb.w;
        }
    }
    for (int k0 = 0; k0 < CH; k0 += KT) {
        __syncthreads();
        for (int i = tid; i < KT * CS / 4; i += 256)
            ((float4*)sW)[i] = ((const float4*)(W3 + k0 * CS))[i];
        __syncthreads();
#pragma unroll
        for (int kk = 0; kk < KT; kk++) {
            int k = k0 + kk;
            float av[8];
#pragma unroll
            for (int r = 0; r < 8; r++) av[r] = sH[(ty * 8 + r) * CH + k];
            float4 w = *(float4*)&sW[kk * CS + tx * 4];
#pragma unroll
            for (int r = 0; r < 8; r++) {
                acc3[r][0] += av[r] * w.x; acc3[r][1] += av[r] * w.y;
                acc3[r][2] += av[r] * w.z; acc3[r][3] += av[r] * w.w;
            }
        }
    }
#pragma unroll
    for (int r = 0; r < 8; r++) {
        int d = sDst[ty * 8 + r];
        float* base = g_sum + (size_t)d * CS + tx * 4;
#pragma unroll
        for (int c = 0; c < 4; c++) atomicAdd(base + c, acc3[r][c]);
    }
}

// -------- finalize: segment mean --------
__global__ void k_final(float* __restrict__ out) {
    int i = blockIdx.x * blockDim.x + threadIdx.x;
    if (i < NN * CS) out[i] = g_sum[i] / fmaxf(g_cnt[i >> 7], 1.0f);
}

extern "C" void kernel_launch(void* const* d_in, const int* in_sizes, int n_in,
                              void* d_out, int out_size) {
    const float* scal  = (const float*)d_in[0];
    const float* nvec  = (const float*)d_in[1];
    const float* ef    = (const float*)d_in[2];
    const int*   ei    = (const int*)d_in[3];
    const float* rot   = (const float*)d_in[4];
    const float* trans = (const float*)d_in[5];
    const float* Wpts  = (const float*)d_in[6];
    const float* bpts  = (const float*)d_in[7];
    const float* Wcomb = (const float*)d_in[8];
    const float* Wspts = (const float*)d_in[9];
    const float* W1    = (const float*)d_in[10];
    const float* b1    = (const float*)d_in[11];
    const float* W2    = (const float*)d_in[12];
    const float* b2    = (const float*)d_in[13];
    const float* W3    = (const float*)d_in[14];
    const float* b3    = (const float*)d_in[15];
    float* out = (float*)d_out;

    const int smem_edge = (TILE * AP + TILE * CH + KT * CH) * 4;  // 110592 B
    cudaFuncSetAttribute(k_edge, cudaFuncAttributeMaxDynamicSharedMemorySize, smem_edge);

    k_setup<<<1, 256>>>(W1);
    k_zero<<<256, 256>>>();
    k_node<<<NN / NT, 256>>>(scal, nvec, rot, trans, Wpts, bpts, Wcomb, Wspts,
                             W1, b1, out + (size_t)NN * CS);
    k_edge<<<NE / TILE, 256, smem_edge>>>(ef, ei, rot, W2, b2, W3, b3);
    k_final<<<(NN * CS + 255) / 256, 256>>>(out);
}

// round 2
// speedup vs baseline: 1.2249x; 1.2249x over previous
#include <cuda_runtime.h>
#include <cstdint>

#define NN 20000
#define NE 320000
#define CS 128
#define CZ 64
#define CH 256
#define CV 16
#define K1 112          // 64 edge feats + 48 rotated src points
#define TILE 64         // edges per block in edge kernel
#define AP 112          // sA row pitch (floats)
#define KT 8            // k-tile for weight staging (double-buffered)
#define NT 8            // nodes per block in node kernel

// -------- scratch (device globals; no allocation allowed) --------
__device__ float g_pre_d[NN * CH];
__device__ float g_pre_s[NN * CH];
__device__ float g_vecs[NN * 48];
__device__ float g_Wcat[K1 * CH];
__device__ float g_SJ[3 * CH];
__device__ float g_sum[NN * CS];
__device__ float g_cnt[NN];

using ull = unsigned long long;

// -------- packed f32x2 helpers --------
__device__ __forceinline__ ull dup2(float x) {
    ull r; unsigned u = __float_as_uint(x);
    asm("mov.b64 %0, {%1, %1};" : "=l"(r) : "r"(u));
    return r;
}
__device__ __forceinline__ ull pack2(float x, float y) {
    ull r;
    asm("mov.b64 %0, {%1, %2};" : "=l"(r)
        : "r"(__float_as_uint(x)), "r"(__float_as_uint(y)));
    return r;
}
__device__ __forceinline__ float2 unpack2(ull p) {
    unsigned lo, hi;
    asm("mov.b64 {%0, %1}, %2;" : "=r"(lo), "=r"(hi) : "l"(p));
    return make_float2(__uint_as_float(lo), __uint_as_float(hi));
}
#define FFMA2(acc, a, b) asm("fma.rn.f32x2 %0, %1, %2, %0;" : "+l"(acc) : "l"(a), "l"(b))

// -------- cp.async helpers --------
__device__ __forceinline__ void cp16(uint32_t dst, const float* src) {
    asm volatile("cp.async.cg.shared.global [%0], [%1], 16;" :: "r"(dst), "l"(src));
}
#define CP_COMMIT() asm volatile("cp.async.commit_group;" ::: "memory")
#define CP_WAIT0()  asm volatile("cp.async.wait_group 0;" ::: "memory")

// -------- setup: derived weights --------
__global__ void k_setup(const float* __restrict__ W1) {
    int h = threadIdx.x;
    for (int r = 0; r < 64; r++)
        g_Wcat[r * CH + h] = W1[(256 + r) * CH + h];
    float sj0 = 0.f, sj1 = 0.f, sj2 = 0.f;
    for (int r = 0; r < 48; r++) {
        float v = W1[(368 + r) * CH + h] + W1[(416 + r) * CH + h];
        g_Wcat[(64 + r) * CH + h] = v;
        int i = r % 3;
        if (i == 0) sj0 += v; else if (i == 1) sj1 += v; else sj2 += v;
    }
    g_SJ[0 * CH + h] = sj0;
    g_SJ[1 * CH + h] = sj1;
    g_SJ[2 * CH + h] = sj2;
}

// -------- zero accumulators --------
__global__ void k_zero() {
    int i = blockIdx.x * blockDim.x + threadIdx.x;
    int stride = gridDim.x * blockDim.x;
    for (int j = i; j < NN * CS; j += stride) g_sum[j] = 0.f;
    for (int j = i; j < NN; j += stride) g_cnt[j] = 0.f;
}

// -------- node kernel: geometry + per-node precompute --------
__global__ void __launch_bounds__(256) k_node(
    const float* __restrict__ scal, const float* __restrict__ nvec,
    const float* __restrict__ rot, const float* __restrict__ trans,
    const float* __restrict__ Wpts, const float* __restrict__ bpts,
    const float* __restrict__ Wcomb, const float* __restrict__ Wspts,
    const float* __restrict__ W1, const float* __restrict__ b1,
    float* __restrict__ out_v)
{
    __shared__ float sScal[NT][CS];
    __shared__ float sRaw[NT][24];
    __shared__ float sCat[NT][72];
    __shared__ float sVec[NT][48];
    __shared__ float sLoc[NT][48];
    __shared__ float sU[NT][4];

    int tid = threadIdx.x;
    int g = tid >> 5, lane = tid & 31;
    int n = blockIdx.x * NT + g;

    {
        float4* d4 = (float4*)sScal[g];
        const float4* s4 = (const float4*)(scal + (size_t)n * CS);
        for (int i = lane; i < CS / 4; i += 32) d4[i] = s4[i];
    }
    __syncwarp();

    if (lane < 24) {
        float acc = bpts[lane];
        for (int k = 0; k < CS; k++) acc += sScal[g][k] * Wpts[k * 24 + lane];
        sRaw[g][lane] = acc;
    }
    __syncwarp();

    float R[9];
#pragma unroll
    for (int j = 0; j < 9; j++) R[j] = rot[(size_t)n * 9 + j];
    float t0 = trans[n * 3 + 0], t1 = trans[n * 3 + 1], t2 = trans[n * 3 + 2];

    for (int idx = lane; idx < 72; idx += 32) {
        int c = idx / 3, d = idx % 3;
        float v;
        if (c < CV) {
            v = nvec[(size_t)n * 48 + idx];
        } else {
            int p = c - CV;
            v = R[d * 3 + 0] * sRaw[g][0 * 8 + p] + R[d * 3 + 1] * sRaw[g][1 * 8 + p]
              + R[d * 3 + 2] * sRaw[g][2 * 8 + p];
        }
        sCat[g][idx] = v;
    }
    __syncwarp();

    for (int idx = lane; idx < 48; idx += 32) {
        int v = idx / 3, d = idx % 3;
        float td = (d == 0) ? t0 : (d == 1) ? t1 : t2;
        float acc = td * 0.1f;
        float acc2 = 0.f;
        for (int c = 0; c < 24; c++) {
            float cv = sCat[g][c * 3 + d];
            acc += cv * Wcomb[c * CV + v];
            acc2 += cv * Wspts[c * CV + v];
        }
        sVec[g][idx] = acc;
        g_vecs[(size_t)n * 48 + idx] = acc;
        out_v[(size_t)n * 48 + idx] = acc2;
    }
    __syncwarp();

    for (int idx = lane; idx < 48; idx += 32) {
        int c = idx / 3, i = idx % 3;
        float x0 = sVec[g][c * 3 + 0] - t0;
        float x1 = sVec[g][c * 3 + 1] - t1;
        float x2 = sVec[g][c * 3 + 2] - t2;
        sLoc[g][idx] = R[0 + i] * x0 + R[3 + i] * x1 + R[6 + i] * x2;
    }
    if (lane < 3) sU[g][lane] = R[0 + lane] * t0 + R[3 + lane] * t1 + R[6 + lane] * t2;
    __syncthreads();

    int h = tid;
    float ad[NT], as_[NT];
#pragma unroll
    for (int q = 0; q < NT; q++) { ad[q] = b1[h]; as_[q] = 0.f; }
    for (int k = 0; k < CS; k++) {
        float wa = W1[k * CH + h];
        float wb = W1[(CS + k) * CH + h];
#pragma unroll
        for (int q = 0; q < NT; q++) {
            float s = sScal[q][k];
            ad[q] += s * wa;
            as_[q] += s * wb;
        }
    }
    for (int r = 0; r < 48; r++) {
        float wI = W1[(320 + r) * CH + h] - W1[(416 + r) * CH + h];
#pragma unroll
        for (int q = 0; q < NT; q++) ad[q] += sLoc[q][r] * wI;
    }
#pragma unroll
    for (int i = 0; i < 3; i++) {
        float sj = g_SJ[i * CH + h];
#pragma unroll
        for (int q = 0; q < NT; q++) ad[q] -= sU[q][i] * sj;
    }
    int nb = blockIdx.x * NT;
#pragma unroll
    for (int q = 0; q < NT; q++) {
        g_pre_d[(size_t)(nb + q) * CH + h] = ad[q];
        g_pre_s[(size_t)(nb + q) * CH + h] = as_[q];
    }
}

// -------- edge kernel: 3 fused GEMMs (f32x2, cp.async pipelined) --------
__global__ void __launch_bounds__(256, 2) k_edge(
    const float* __restrict__ ef, const int* __restrict__ ei,
    const float* __restrict__ rot,
    const float* __restrict__ W2, const float* __restrict__ b2,
    const float* __restrict__ W3, const float* __restrict__ b3)
{
    extern __shared__ float sm[];
    float* sA  = sm;                       // TILE*AP   = 7168
    float* sH  = sm + TILE * AP;           // TILE*CH   = 16384
    float* sW0 = sH + TILE * CH;           // KT*CH     = 2048
    float* sW1 = sW0 + KT * CH;            // KT*CH     = 2048
    __shared__ int sDst[TILE], sSrc[TILE];

    int tid = threadIdx.x;
    int e0 = blockIdx.x * TILE;
    uint32_t w0a = (uint32_t)__cvta_generic_to_shared(sW0);
    uint32_t w1a = (uint32_t)__cvta_generic_to_shared(sW1);

    if (tid < TILE) {
        sSrc[tid] = ei[e0 + tid];
        sDst[tid] = ei[NE + e0 + tid];
    }

    // prefetch GEMM1 weight tile 0 into sW0 (2048 floats, 2 x 16B per thread)
    cp16(w0a + tid * 16, g_Wcat + tid * 4);
    cp16(w0a + (tid + 256) * 16, g_Wcat + (tid + 256) * 4);
    CP_COMMIT();

    __syncthreads();   // sSrc/sDst visible

    // stage edge features into sA[:, 0:64]
    {
        const float4* ef4 = (const float4*)(ef + (size_t)e0 * CZ);
        for (int i = tid; i < TILE * CZ / 4; i += 256) {
            int row = i >> 4, c4 = i & 15;
            *(float4*)&sA[row * AP + c4 * 4] = ef4[row * 16 + c4];
        }
    }
    // y = R_dst^T vecs_src  into sA[:, 64:112]   (4 threads per edge)
    {
        int r = tid >> 2, q = tid & 3;
        int s = sSrc[r], d = sDst[r];
        float R[9];
#pragma unroll
        for (int j = 0; j < 9; j++) R[j] = rot[(size_t)d * 9 + j];
#pragma unroll
        for (int cc = 0; cc < 4; cc++) {
            int c = q * 4 + cc;
            float v0 = g_vecs[(size_t)s * 48 + c * 3 + 0];
            float v1 = g_vecs[(size_t)s * 48 + c * 3 + 1];
            float v2 = g_vecs[(size_t)s * 48 + c * 3 + 2];
#pragma unroll
            for (int i = 0; i < 3; i++)
                sA[r * AP + 64 + c * 3 + i] = R[0 + i] * v0 + R[3 + i] * v1 + R[6 + i] * v2;
        }
        if (q == 0) atomicAdd(&g_cnt[d], 1.0f);
    }

    int ty = tid >> 5, tx = tid & 31;
    int c0 = tx * 4;            // thread owns cols [c0, c0+4) and [128+c0, 128+c0+4)

    // ---- GEMM1: [64,112] x [112,256], acc init = pre_d[dst] + pre_s[src] ----
    ull acc[8][4];
#pragma unroll
    for (int r = 0; r < 8; r++) {
        int row = ty * 8 + r;
        const float* pd = g_pre_d + (size_t)sDst[row] * CH;
        const float* ps = g_pre_s + (size_t)sSrc[row] * CH;
        float4 d0 = *(const float4*)(pd + c0);
        float4 d1 = *(const float4*)(pd + 128 + c0);
        float4 s0 = *(const float4*)(ps + c0);
        float4 s1 = *(const float4*)(ps + 128 + c0);
        acc[r][0] = pack2(d0.x + s0.x, d0.y + s0.y);
        acc[r][1] = pack2(d0.z + s0.z, d0.w + s0.w);
        acc[r][2] = pack2(d1.x + s1.x, d1.y + s1.y);
        acc[r][3] = pack2(d1.z + s1.z, d1.w + s1.w);
    }

    const int T1 = K1 / KT;   // 14
    for (int t = 0; t < T1; t++) {
        CP_WAIT0();
        __syncthreads();      // tile t visible; all warps done with prev tile (also covers sA-ready at t=0)
        if (t + 1 < T1) {
            uint32_t dst = ((t + 1) & 1) ? w1a : w0a;
            const float* src = g_Wcat + (t + 1) * KT * CH;
            cp16(dst + tid * 16, src + tid * 4);
            cp16(dst + (tid + 256) * 16, src + (tid + 256) * 4);
            CP_COMMIT();
        }
        const float* Wb = (t & 1) ? sW1 : sW0;
#pragma unroll
        for (int kk = 0; kk < KT; kk++) {
            int k = t * KT + kk;
            ulonglong2 wv0 = *(const ulonglong2*)&Wb[kk * CH + c0];
            ulonglong2 wv1 = *(const ulonglong2*)&Wb[kk * CH + 128 + c0];
#pragma unroll
            for (int r = 0; r < 8; r++) {
                ull a = dup2(sA[(ty * 8 + r) * AP + k]);
                FFMA2(acc[r][0], a, wv0.x);
                FFMA2(acc[r][1], a, wv0.y);
                FFMA2(acc[r][2], a, wv1.x);
                FFMA2(acc[r][3], a, wv1.y);
            }
        }
    }
    // epilogue: relu -> sH
#pragma unroll
    for (int r = 0; r < 8; r++) {
        int row = ty * 8 + r;
        float2 p0 = unpack2(acc[r][0]), p1 = unpack2(acc[r][1]);
        float2 p2 = unpack2(acc[r][2]), p3 = unpack2(acc[r][3]);
        *(float4*)&sH[row * CH + c0] =
            make_float4(fmaxf(p0.x, 0.f), fmaxf(p0.y, 0.f), fmaxf(p1.x, 0.f), fmaxf(p1.y, 0.f));
        *(float4*)&sH[row * CH + 128 + c0] =
            make_float4(fmaxf(p2.x, 0.f), fmaxf(p2.y, 0.f), fmaxf(p3.x, 0.f), fmaxf(p3.y, 0.f));
    }
    __syncthreads();          // sH visible; sW buffers free

    // prefetch GEMM2 tile 0
    cp16(w0a + tid * 16, W2 + tid * 4);
    cp16(w0a + (tid + 256) * 16, W2 + (tid + 256) * 4);
    CP_COMMIT();

    // ---- GEMM2: [64,256] x [256,256] ----
    ull acc2[8][4];
    {
        float4 bb0 = *(const float4*)&b2[c0];
        float4 bb1 = *(const float4*)&b2[128 + c0];
        ull i0 = pack2(bb0.x, bb0.y), i1 = pack2(bb0.z, bb0.w);
        ull i2 = pack2(bb1.x, bb1.y), i3 = pack2(bb1.z, bb1.w);
#pragma unroll
        for (int r = 0; r < 8; r++) {
            acc2[r][0] = i0; acc2[r][1] = i1; acc2[r][2] = i2; acc2[r][3] = i3;
        }
    }
    const int T2 = CH / KT;   // 32
    for (int t = 0; t < T2; t++) {
        CP_WAIT0();
        __syncthreads();
        if (t + 1 < T2) {
            uint32_t dst = ((t + 1) & 1) ? w1a : w0a;
            const float* src = W2 + (t + 1) * KT * CH;
            cp16(dst + tid * 16, src + tid * 4);
            cp16(dst + (tid + 256) * 16, src + (tid + 256) * 4);
            CP_COMMIT();
        }
        const float* Wb = (t & 1) ? sW1 : sW0;
#pragma unroll
        for (int kk = 0; kk < KT; kk++) {
            int k = t * KT + kk;
            ulonglong2 wv0 = *(const ulonglong2*)&Wb[kk * CH + c0];
            ulonglong2 wv1 = *(const ulonglong2*)&Wb[kk * CH + 128 + c0];
#pragma unroll
            for (int r = 0; r < 8; r++) {
                ull a = dup2(sH[(ty * 8 + r) * CH + k]);
                FFMA2(acc2[r][0], a, wv0.x);
                FFMA2(acc2[r][1], a, wv0.y);
                FFMA2(acc2[r][2], a, wv1.x);
                FFMA2(acc2[r][3], a, wv1.y);
            }
        }
    }
    __syncthreads();          // all warps done reading sH (GEMM2 inputs) before overwrite
#pragma unroll
    for (int r = 0; r < 8; r++) {
        int row = ty * 8 + r;
        float2 p0 = unpack2(acc2[r][0]), p1 = unpack2(acc2[r][1]);
        float2 p2 = unpack2(acc2[r][2]), p3 = unpack2(acc2[r][3]);
        *(float4*)&sH[row * CH + c0] =
            make_float4(fmaxf(p0.x, 0.f), fmaxf(p0.y, 0.f), fmaxf(p1.x, 0.f), fmaxf(p1.y, 0.f));
        *(float4*)&sH[row * CH + 128 + c0] =
            make_float4(fmaxf(p2.x, 0.f), fmaxf(p2.y, 0.f), fmaxf(p3.x, 0.f), fmaxf(p3.y, 0.f));
    }
    __syncthreads();

    // prefetch GEMM3 tile 0 (KT*CS = 1024 floats, 1 x 16B per thread)
    cp16(w0a + tid * 16, W3 + tid * 4);
    CP_COMMIT();

    // ---- GEMM3: [64,256] x [256,128], then atomic scatter ----
    ull acc3[8][2];
    {
        float4 bb = *(const float4*)&b3[c0];
        ull i0 = pack2(bb.x, bb.y), i1 = pack2(bb.z, bb.w);
#pragma unroll
        for (int r = 0; r < 8; r++) { acc3[r][0] = i0; acc3[r][1] = i1; }
    }
    const int T3 = CH / KT;   // 32
    for (int t = 0; t < T3; t++) {
        CP_WAIT0();
        __syncthreads();
        if (t + 1 < T3) {
            uint32_t dst = ((t + 1) & 1) ? w1a : w0a;
            const float* src = W3 + (t + 1) * KT * CS;
            cp16(dst + tid * 16, src + tid * 4);
            CP_COMMIT();
        }
        const float* Wb = (t & 1) ? sW1 : sW0;
#pragma unroll
        for (int kk = 0; kk < KT; kk++) {
            int k = t * KT + kk;
            ulonglong2 wv = *(const ulonglong2*)&Wb[kk * CS + c0];
#pragma unroll
            for (int r = 0; r < 8; r++) {
                ull a = dup2(sH[(ty * 8 + r) * CH + k]);
                FFMA2(acc3[r][0], a, wv.x);
                FFMA2(acc3[r][1], a, wv.y);
            }
        }
    }
#pragma unroll
    for (int r = 0; r < 8; r++) {
        int d = sDst[ty * 8 + r];
        float* base = g_sum + (size_t)d * CS + c0;
        float2 p0 = unpack2(acc3[r][0]), p1 = unpack2(acc3[r][1]);
        atomicAdd(base + 0, p0.x);
        atomicAdd(base + 1, p0.y);
        atomicAdd(base + 2, p1.x);
        atomicAdd(base + 3, p1.y);
    }
}

// -------- finalize: segment mean --------
__global__ void k_final(float* __restrict__ out) {
    int i = blockIdx.x * blockDim.x + threadIdx.x;
    if (i < NN * CS) out[i] = g_sum[i] / fmaxf(g_cnt[i >> 7], 1.0f);
}

extern "C" void kernel_launch(void* const* d_in, const int* in_sizes, int n_in,
                              void* d_out, int out_size) {
    const float* scal  = (const float*)d_in[0];
    const float* nvec  = (const float*)d_in[1];
    const float* ef    = (const float*)d_in[2];
    const int*   ei    = (const int*)d_in[3];
    const float* rot   = (const float*)d_in[4];
    const float* trans = (const float*)d_in[5];
    const float* Wpts  = (const float*)d_in[6];
    const float* bpts  = (const float*)d_in[7];
    const float* Wcomb = (const float*)d_in[8];
    const float* Wspts = (const float*)d_in[9];
    const float* W1    = (const float*)d_in[10];
    const float* b1    = (const float*)d_in[11];
    const float* W2    = (const float*)d_in[12];
    const float* b2    = (const float*)d_in[13];
    const float* W3    = (const float*)d_in[14];
    const float* b3    = (const float*)d_in[15];
    float* out = (float*)d_out;

    const int smem_edge = (TILE * AP + TILE * CH + 2 * KT * CH) * 4;  // 110592 B
    cudaFuncSetAttribute(k_edge, cudaFuncAttributeMaxDynamicSharedMemorySize, smem_edge);

    k_setup<<<1, 256>>>(W1);
    k_zero<<<256, 256>>>();
    k_node<<<NN / NT, 256>>>(scal, nvec, rot, trans, Wpts, bpts, Wcomb, Wspts,
                             W1, b1, out + (size_t)NN * CS);
    k_edge<<<NE / TILE, 256, smem_edge>>>(ef, ei, rot, W2, b2, W3, b3);
    k_final<<<(NN * CS + 255) / 256, 256>>>(out);
}

// round 15
// speedup vs baseline: 1.9733x; 1.6110x over previous
#include <cuda_runtime.h>
#include <cstdint>

#define NN 20000
#define NE 320000
#define CS 128
#define CZ 64
#define CH 256
#define CV 16
#define TILE 64         // edges per CTA
#define NT 8            // nodes per block in node kernel

// -------- scratch (device globals) --------
__device__ float g_pre_d[NN * CH];
__device__ float g_pre_s[NN * CH];
__device__ float g_vecs[NN * 48];
__device__ float g_Wcat[112 * CH];    // K-major derived GEMM1 weights (fp32)
__device__ float g_SJ[3 * CH];
__device__ float g_sum[NN * CS];
__device__ float g_cnt[NN];
// chunked tf32 B images: [chunk][n][32] (32 k-values per chunk)
__device__ float g_W1B[4 * CH * 32];  // N=256, K=128 (112 real + zero pad)
__device__ float g_W2B[8 * CH * 32];  // N=256, K=256
__device__ float g_W3B[8 * CS * 32];  // N=128, K=256

// -------- helpers --------
__device__ __forceinline__ float tf32r(float x) {
    uint32_t u;
    asm("cvt.rna.tf32.f32 %0, %1;" : "=r"(u) : "f"(x));
    return __uint_as_float(u);
}
__device__ __forceinline__ void cp16(uint32_t dst, const void* src) {
    asm volatile("cp.async.cg.shared.global [%0], [%1], 16;" :: "r"(dst), "l"(src));
}
#define CP_COMMIT() asm volatile("cp.async.commit_group;" ::: "memory")
#define CP_WAIT0()  asm volatile("cp.async.wait_group 0;" ::: "memory")

#define MMA_TF32(d, a, b0, b1) \
    asm volatile("mma.sync.aligned.m16n8k8.row.col.f32.tf32.tf32.f32 " \
                 "{%0,%1,%2,%3},{%4,%5,%6,%7},{%8,%9},{%0,%1,%2,%3};" \
                 : "+f"((d)[0]), "+f"((d)[1]), "+f"((d)[2]), "+f"((d)[3]) \
                 : "r"((a)[0]), "r"((a)[1]), "r"((a)[2]), "r"((a)[3]), \
                   "r"(b0), "r"(b1))

#define BPITCH 36   // smem B chunk row pitch (32 + 4 pad, conflict-free)
#define APITCH 132  // sA pitch (128 + 4)
#define HPITCH 260  // sH pitch (256 + 4)

// stage one 32-k chunk of a B image into smem (Nrows x 32 -> pitch 36)
__device__ __forceinline__ void load_chunk(const float* gW, int c, int Nrows,
                                           float* buf, int tid) {
    uint32_t ba = (uint32_t)__cvta_generic_to_shared(buf);
    const float* src = gW + (size_t)c * Nrows * 32;
    int total = Nrows * 8;                    // cp16 count
    for (int cp = tid; cp < total; cp += 256) {
        int n = cp >> 3, k4 = (cp & 7) * 4;
        cp16(ba + (uint32_t)(n * BPITCH + k4) * 4, src + n * 32 + k4);
    }
    CP_COMMIT();
}

// warp-tiled tf32 GEMM over chunked B: acc[2][NTL][4], rows m0..m0+31, cols n0..
template <int NTL>
__device__ __forceinline__ void do_gemm(const float* gW, int C, int Nrows,
                                        const float* srcA, int pitchA,
                                        float* sB0, float* sB1,
                                        float acc[2][NTL][4],
                                        int tid, int m0, int n0, int g, int t) {
    for (int c = 0; c < C; c++) {
        CP_WAIT0();
        __syncthreads();          // chunk c visible; all warps done with chunk c-1
        if (c + 1 < C) load_chunk(gW, c + 1, Nrows, ((c + 1) & 1) ? sB1 : sB0, tid);
        const float* bb = (c & 1) ? sB1 : sB0;
#pragma unroll
        for (int ks = 0; ks < 4; ks++) {
            int kb = ks * 8;          // chunk-local k (B image is per-chunk)
            int ka = c * 32 + kb;     // global k (A is a full-width row)
            uint32_t a[2][4];
#pragma unroll
            for (int mt = 0; mt < 2; mt++) {
                const float* ap = srcA + (m0 + mt * 16 + g) * pitchA + ka + t;
                a[mt][0] = __float_as_uint(ap[0]);
                a[mt][1] = __float_as_uint(ap[8 * pitchA]);
                a[mt][2] = __float_as_uint(ap[4]);
                a[mt][3] = __float_as_uint(ap[8 * pitchA + 4]);
            }
#pragma unroll
            for (int nt = 0; nt < NTL; nt++) {
                const float* bp = bb + (n0 + nt * 8 + g) * BPITCH + kb + t;
                uint32_t b0 = __float_as_uint(bp[0]);
                uint32_t b1 = __float_as_uint(bp[4]);
                MMA_TF32(acc[0][nt], a[0], b0, b1);
                MMA_TF32(acc[1][nt], a[1], b0, b1);
            }
        }
    }
    __syncthreads();              // all MMAs done before epilogue rewrites activations
}

// -------- setup: derived weights --------
__global__ void k_setup(const float* __restrict__ W1) {
    int h = threadIdx.x;
    for (int r = 0; r < 64; r++)
        g_Wcat[r * CH + h] = W1[(256 + r) * CH + h];
    float sj0 = 0.f, sj1 = 0.f, sj2 = 0.f;
    for (int r = 0; r < 48; r++) {
        float v = W1[(368 + r) * CH + h] + W1[(416 + r) * CH + h];
        g_Wcat[(64 + r) * CH + h] = v;
        int i = r % 3;
        if (i == 0) sj0 += v; else if (i == 1) sj1 += v; else sj2 += v;
    }
    g_SJ[0 * CH + h] = sj0;
    g_SJ[1 * CH + h] = sj1;
    g_SJ[2 * CH + h] = sj2;
}

// -------- pack weights into chunked tf32 images --------
__global__ void k_pack(const float* __restrict__ W2, const float* __restrict__ W3) {
    int i = blockIdx.x * blockDim.x + threadIdx.x;   // 65536 threads
    {   // W2B: [c][n][32], c = i>>13, n = (i>>5)&255, kc = i&31
        int k = (i >> 13) * 32 + (i & 31);
        int n = (i >> 5) & 255;
        g_W2B[i] = tf32r(W2[k * CH + n]);
    }
    if (i < 4 * CH * 32) {   // W1B
        int k = (i >> 13) * 32 + (i & 31);
        int n = (i >> 5) & 255;
        g_W1B[i] = tf32r(k < 112 ? g_Wcat[k * CH + n] : 0.f);
    }
    if (i < 8 * CS * 32) {   // W3B: chunk = i>>12, n = (i>>5)&127
        int k = (i >> 12) * 32 + (i & 31);
        int n = (i >> 5) & 127;
        g_W3B[i] = tf32r(W3[k * CS + n]);
    }
}

// -------- zero accumulators --------
__global__ void k_zero() {
    int i = blockIdx.x * blockDim.x + threadIdx.x;
    int stride = gridDim.x * blockDim.x;
    for (int j = i; j < NN * CS; j += stride) g_sum[j] = 0.f;
    for (int j = i; j < NN; j += stride) g_cnt[j] = 0.f;
}

// -------- node kernel --------
__global__ void __launch_bounds__(256) k_node(
    const float* __restrict__ scal, const float* __restrict__ nvec,
    const float* __restrict__ rot, const float* __restrict__ trans,
    const float* __restrict__ Wpts, const float* __restrict__ bpts,
    const float* __restrict__ Wcomb, const float* __restrict__ Wspts,
    const float* __restrict__ W1, const float* __restrict__ b1,
    float* __restrict__ out_v)
{
    __shared__ float sScal[NT][CS];
    __shared__ float sRaw[NT][24];
    __shared__ float sCat[NT][72];
    __shared__ float sVec[NT][48];
    __shared__ float sLoc[NT][48];
    __shared__ float sU[NT][4];

    int tid = threadIdx.x;
    int g = tid >> 5, lane = tid & 31;
    int n = blockIdx.x * NT + g;

    {
        float4* d4 = (float4*)sScal[g];
        const float4* s4 = (const float4*)(scal + (size_t)n * CS);
        for (int i = lane; i < CS / 4; i += 32) d4[i] = s4[i];
    }
    __syncwarp();

    if (lane < 24) {
        float acc = bpts[lane];
        for (int k = 0; k < CS; k++) acc += sScal[g][k] * Wpts[k * 24 + lane];
        sRaw[g][lane] = acc;
    }
    __syncwarp();

    float R[9];
#pragma unroll
    for (int j = 0; j < 9; j++) R[j] = rot[(size_t)n * 9 + j];
    float t0 = trans[n * 3 + 0], t1 = trans[n * 3 + 1], t2 = trans[n * 3 + 2];

    for (int idx = lane; idx < 72; idx += 32) {
        int c = idx / 3, d = idx % 3;
        float v;
        if (c < CV) {
            v = nvec[(size_t)n * 48 + idx];
        } else {
            int p = c - CV;
            v = R[d * 3 + 0] * sRaw[g][0 * 8 + p] + R[d * 3 + 1] * sRaw[g][1 * 8 + p]
              + R[d * 3 + 2] * sRaw[g][2 * 8 + p];
        }
        sCat[g][idx] = v;
    }
    __syncwarp();

    for (int idx = lane; idx < 48; idx += 32) {
        int v = idx / 3, d = idx % 3;
        float td = (d == 0) ? t0 : (d == 1) ? t1 : t2;
        float acc = td * 0.1f;
        float acc2 = 0.f;
        for (int c = 0; c < 24; c++) {
            float cv = sCat[g][c * 3 + d];
            acc += cv * Wcomb[c * CV + v];
            acc2 += cv * Wspts[c * CV + v];
        }
        sVec[g][idx] = acc;
        g_vecs[(size_t)n * 48 + idx] = acc;
        out_v[(size_t)n * 48 + idx] = acc2;
    }
    __syncwarp();

    for (int idx = lane; idx < 48; idx += 32) {
        int c = idx / 3, i = idx % 3;
        float x0 = sVec[g][c * 3 + 0] - t0;
        float x1 = sVec[g][c * 3 + 1] - t1;
        float x2 = sVec[g][c * 3 + 2] - t2;
        sLoc[g][idx] = R[0 + i] * x0 + R[3 + i] * x1 + R[6 + i] * x2;
    }
    if (lane < 3) sU[g][lane] = R[0 + lane] * t0 + R[3 + lane] * t1 + R[6 + lane] * t2;
    __syncthreads();

    int h = tid;
    float ad[NT], as_[NT];
#pragma unroll
    for (int q = 0; q < NT; q++) { ad[q] = b1[h]; as_[q] = 0.f; }
    for (int k = 0; k < CS; k++) {
        float wa = W1[k * CH + h];
        float wb = W1[(CS + k) * CH + h];
#pragma unroll
        for (int q = 0; q < NT; q++) {
            float s = sScal[q][k];
            ad[q] += s * wa;
            as_[q] += s * wb;
        }
    }
    for (int r = 0; r < 48; r++) {
        float wI = W1[(320 + r) * CH + h] - W1[(416 + r) * CH + h];
#pragma unroll
        for (int q = 0; q < NT; q++) ad[q] += sLoc[q][r] * wI;
    }
#pragma unroll
    for (int i = 0; i < 3; i++) {
        float sj = g_SJ[i * CH + h];
#pragma unroll
        for (int q = 0; q < NT; q++) ad[q] -= sU[q][i] * sj;
    }
    int nb = blockIdx.x * NT;
#pragma unroll
    for (int q = 0; q < NT; q++) {
        g_pre_d[(size_t)(nb + q) * CH + h] = ad[q];
        g_pre_s[(size_t)(nb + q) * CH + h] = as_[q];
    }
}

// -------- edge kernel: fused 3-layer MLP on mma.sync tf32 --------
__global__ void __launch_bounds__(256) k_edge(
    const float* __restrict__ ef, const int* __restrict__ ei,
    const float* __restrict__ rot,
    const float* __restrict__ b2, const float* __restrict__ b3)
{
    extern __shared__ float sm[];
    float* sA  = sm;                          // 64 x APITCH
    float* sH  = sA + TILE * APITCH;          // 64 x HPITCH
    float* sB0 = sH + TILE * HPITCH;          // 256 x BPITCH
    float* sB1 = sB0 + CH * BPITCH;           // 256 x BPITCH
    __shared__ int sDst[TILE], sSrc[TILE];
    __shared__ float s_b2[CH];
    __shared__ float s_b3[CS];

    int tid = threadIdx.x, wid = tid >> 5, lane = tid & 31;
    int g = lane >> 2, t = lane & 3;
    int wm = wid >> 2, wn = wid & 3;
    int m0 = wm * 32;
    int e0 = blockIdx.x * TILE;

    // prefetch GEMM1 chunk 0 immediately
    load_chunk(g_W1B, 0, CH, sB0, tid);

    if (tid < TILE) {
        sSrc[tid] = ei[e0 + tid];
        sDst[tid] = ei[NE + e0 + tid];
    }
    s_b2[tid] = b2[tid];
    if (tid < CS) s_b3[tid] = b3[tid];
    __syncthreads();

    // ---- build A1 (tf32): cols 0..63 edge feats, 64..111 rotated loc, 112..127 zero ----
    {
        const float4* ef4 = (const float4*)(ef + (size_t)e0 * CZ);
        for (int i = tid; i < TILE * 16; i += 256) {
            int r = i >> 4, c4 = (i & 15) * 4;
            float4 v = ef4[i];
            float* dst = sA + r * APITCH + c4;
            dst[0] = tf32r(v.x); dst[1] = tf32r(v.y);
            dst[2] = tf32r(v.z); dst[3] = tf32r(v.w);
        }
    }
    {
        int r = tid >> 2, q = tid & 3;
        int s = sSrc[r], d = sDst[r];
        float R[9];
#pragma unroll
        for (int j = 0; j < 9; j++) R[j] = rot[(size_t)d * 9 + j];
#pragma unroll
        for (int cc = 0; cc < 4; cc++) {
            int c = q * 4 + cc;
            float v0 = g_vecs[(size_t)s * 48 + c * 3 + 0];
            float v1 = g_vecs[(size_t)s * 48 + c * 3 + 1];
            float v2 = g_vecs[(size_t)s * 48 + c * 3 + 2];
#pragma unroll
            for (int i = 0; i < 3; i++)
                sA[r * APITCH + 64 + c * 3 + i] =
                    tf32r(R[0 + i] * v0 + R[3 + i] * v1 + R[6 + i] * v2);
        }
        if (q == 0) atomicAdd(&g_cnt[d], 1.0f);
        // zero pad k = 112..127
        float4 z = make_float4(0.f, 0.f, 0.f, 0.f);
        *(float4*)(sA + r * APITCH + 112 + q * 4) = z;
    }
    // ---- stage P = pre_d[dst] + pre_s[src] into sH (consumed by epi1) ----
    {
        int r = tid >> 2, cb = (tid & 3) * 64;
        const float4* pd = (const float4*)(g_pre_d + (size_t)sDst[r] * CH + cb);
        const float4* ps = (const float4*)(g_pre_s + (size_t)sSrc[r] * CH + cb);
        float4* hp = (float4*)(sH + r * HPITCH + cb);
#pragma unroll
        for (int j = 0; j < 16; j++) {
            float4 a = pd[j], b = ps[j];
            hp[j] = make_float4(a.x + b.x, a.y + b.y, a.z + b.z, a.w + b.w);
        }
    }
    // (do_gemm's first CP_WAIT0 + __syncthreads makes sA/sH visible to all warps)

    // ======== GEMM1: [64,128] x [128,256] ========
    {
        float acc[2][8][4];
#pragma unroll
        for (int mt = 0; mt < 2; mt++)
#pragma unroll
            for (int nt = 0; nt < 8; nt++)
#pragma unroll
                for (int j = 0; j < 4; j++) acc[mt][nt][j] = 0.f;
        do_gemm<8>(g_W1B, 4, CH, sA, APITCH, sB0, sB1, acc, tid, m0, wn * 64, g, t);
        load_chunk(g_W2B, 0, CH, sB0, tid);   // prefetch GEMM2 during epi1
        // epi1: H = relu(acc + P), tf32-rounded, in place in sH
        int n0 = wn * 64;
#pragma unroll
        for (int mt = 0; mt < 2; mt++)
#pragma unroll
            for (int nt = 0; nt < 8; nt++) {
                int r0 = m0 + mt * 16 + g;
                int cc = n0 + nt * 8 + 2 * t;
                float* h0 = sH + r0 * HPITCH + cc;
                float* h1 = h0 + 8 * HPITCH;
                h0[0] = tf32r(fmaxf(acc[mt][nt][0] + h0[0], 0.f));
                h0[1] = tf32r(fmaxf(acc[mt][nt][1] + h0[1], 0.f));
                h1[0] = tf32r(fmaxf(acc[mt][nt][2] + h1[0], 0.f));
                h1[1] = tf32r(fmaxf(acc[mt][nt][3] + h1[1], 0.f));
            }
    }

    // ======== GEMM2: [64,256] x [256,256] ========
    {
        float acc[2][8][4];
#pragma unroll
        for (int mt = 0; mt < 2; mt++)
#pragma unroll
            for (int nt = 0; nt < 8; nt++)
#pragma unroll
                for (int j = 0; j < 4; j++) acc[mt][nt][j] = 0.f;
        do_gemm<8>(g_W2B, 8, CH, sH, HPITCH, sB0, sB1, acc, tid, m0, wn * 64, g, t);
        load_chunk(g_W3B, 0, CS, sB0, tid);   // prefetch GEMM3 during epi2
        int n0 = wn * 64;
#pragma unroll
        for (int mt = 0; mt < 2; mt++)
#pragma unroll
            for (int nt = 0; nt < 8; nt++) {
                int r0 = m0 + mt * 16 + g;
                int cc = n0 + nt * 8 + 2 * t;
                float* h0 = sH + r0 * HPITCH + cc;
                float* h1 = h0 + 8 * HPITCH;
                h0[0] = tf32r(fmaxf(acc[mt][nt][0] + s_b2[cc], 0.f));
                h0[1] = tf32r(fmaxf(acc[mt][nt][1] + s_b2[cc + 1], 0.f));
                h1[0] = tf32r(fmaxf(acc[mt][nt][2] + s_b2[cc], 0.f));
                h1[1] = tf32r(fmaxf(acc[mt][nt][3] + s_b2[cc + 1], 0.f));
            }
    }

    // ======== GEMM3: [64,256] x [256,128] + scatter ========
    {
        float acc[2][4][4];
#pragma unroll
        for (int mt = 0; mt < 2; mt++)
#pragma unroll
            for (int nt = 0; nt < 4; nt++)
#pragma unroll
                for (int j = 0; j < 4; j++) acc[mt][nt][j] = 0.f;
        do_gemm<4>(g_W3B, 8, CS, sH, HPITCH, sB0, sB1, acc, tid, m0, wn * 32, g, t);
        int n0 = wn * 32;
#pragma unroll
        for (int mt = 0; mt < 2; mt++)
#pragma unroll
            for (int nt = 0; nt < 4; nt++) {
                int r0 = m0 + mt * 16 + g;
                int cc = n0 + nt * 8 + 2 * t;
                int d0 = sDst[r0], d1 = sDst[r0 + 8];
                atomicAdd(&g_sum[(size_t)d0 * CS + cc],     acc[mt][nt][0] + s_b3[cc]);
                atomicAdd(&g_sum[(size_t)d0 * CS + cc + 1], acc[mt][nt][1] + s_b3[cc + 1]);
                atomicAdd(&g_sum[(size_t)d1 * CS + cc],     acc[mt][nt][2] + s_b3[cc]);
                atomicAdd(&g_sum[(size_t)d1 * CS + cc + 1], acc[mt][nt][3] + s_b3[cc + 1]);
            }
    }
}

// -------- finalize: segment mean --------
__global__ void k_final(float* __restrict__ out) {
    int i = blockIdx.x * blockDim.x + threadIdx.x;
    if (i < NN * CS) out[i] = g_sum[i] / fmaxf(g_cnt[i >> 7], 1.0f);
}

extern "C" void kernel_launch(void* const* d_in, const int* in_sizes, int n_in,
                              void* d_out, int out_size) {
    const float* scal  = (const float*)d_in[0];
    const float* nvec  = (const float*)d_in[1];
    const float* ef    = (const float*)d_in[2];
    const int*   ei    = (const int*)d_in[3];
    const float* rot   = (const float*)d_in[4];
    const float* trans = (const float*)d_in[5];
    const float* Wpts  = (const float*)d_in[6];
    const float* bpts  = (const float*)d_in[7];
    const float* Wcomb = (const float*)d_in[8];
    const float* Wspts = (const float*)d_in[9];
    const float* W1    = (const float*)d_in[10];
    const float* b1    = (const float*)d_in[11];
    const float* W2    = (const float*)d_in[12];
    const float* b2    = (const float*)d_in[13];
    const float* W3    = (const float*)d_in[14];
    const float* b3    = (const float*)d_in[15];
    float* out = (float*)d_out;

    const int smem_edge = (TILE * APITCH + TILE * HPITCH + 2 * CH * BPITCH) * 4; // 174080 B
    cudaFuncSetAttribute(k_edge, cudaFuncAttributeMaxDynamicSharedMemorySize, smem_edge);

    k_setup<<<1, 256>>>(W1);
    k_pack<<<256, 256>>>(W2, W3);
    k_zero<<<256, 256>>>();
    k_node<<<NN / NT, 256>>>(scal, nvec, rot, trans, Wpts, bpts, Wcomb, Wspts,
                             W1, b1, out + (size_t)NN * CS);
    k_edge<<<NE / TILE, 256, smem_edge>>>(ef, ei, rot, b2, b3);
    k_final<<<(NN * CS + 255) / 256, 256>>>(out);
}